// round 11
// baseline (speedup 1.0000x reference)
#include <cuda_runtime.h>
#include <cstdint>

#define HW 65536
#define IMGW 256
#define CH 384

// hidden activations, channel-last: [b][pix][384]  (402.7 MB)
__device__ float g_hidden[(size_t)4 * HW * CH];
__device__ float g_wdw_t[9 * 384];       // [tap][channel]
__device__ float2 g_wout_p[64 * 64];     // [c2][o] = (wout[o][2c2], wout[o][2c2+1])

typedef unsigned long long u64;

__device__ __forceinline__ u64 pack2(float lo, float hi) {
    u64 r; asm("mov.b64 %0, {%1, %2};" : "=l"(r) : "f"(lo), "f"(hi)); return r;
}
__device__ __forceinline__ void ffma2(u64 &d, u64 a, u64 b) {
    asm("fma.rn.f32x2 %0, %1, %2, %0;" : "+l"(d) : "l"(a), "l"(b));
}
__device__ __forceinline__ void unpack2(float &lo, float &hi, u64 v) {
    asm("mov.b64 {%0, %1}, %2;" : "=f"(lo), "=f"(hi) : "l"(v));
}

// ---------------------------------------------------------------------------
// K1: 1x1 conv 64->384 as SGEMM (f32x2 FMAs, zero-mov inner loop).
//   grid (512, 3, 4), block 256, 96KB dynamic smem (Wd 64KB dup-pairs + Xs 32KB).
//   Accumulators are pixel-pairs: A operand = direct u64 of adjacent pixels,
//   B operand = pre-duplicated (w,w) u64 from smem. No packing movs in loop.
//   Block (0,0,0) additionally preps g_wdw_t / g_wout_p for K2.
// ---------------------------------------------------------------------------
__global__ __launch_bounds__(256) void k1_conv1x1(const float* __restrict__ x,
                                                  const float* __restrict__ wh,
                                                  const float* __restrict__ wdw,
                                                  const float* __restrict__ wout) {
    extern __shared__ float sm[];
    u64*   Wd = (u64*)sm;          // [64 c][128 o] duplicated (w,w), 64 KB
    float* Xs = sm + 16384;        // [64 c][128 pix], 32 KB
    const int b  = blockIdx.z;
    const int ob = blockIdx.y;
    const int pb = blockIdx.x;
    const int tid = threadIdx.x;

    if (pb == 0 && ob == 0 && b == 0) {
        for (int i = tid; i < 9 * 384; i += 256) {
            int o = i / 9, k = i % 9;
            g_wdw_t[k * 384 + o] = wdw[i];
        }
        for (int i = tid; i < 64 * 64; i += 256) {
            int c2 = i >> 6, o = i & 63;
            g_wout_p[c2 * 64 + o] = make_float2(wout[o * 128 + 2 * c2],
                                                wout[o * 128 + 2 * c2 + 1]);
        }
    }

    const float* xb = x + (size_t)b * 64 * HW + (size_t)pb * 128;

    // fill Wd: duplicated weight pairs (wh is tiny and L2-hot; reads via __ldg)
    for (int i = tid; i < 64 * 128; i += 256) {
        int c = i >> 7, o = i & 127;
        float w = __ldg(wh + (size_t)(ob * 128 + o) * 64 + c);
        Wd[i] = pack2(w, w);
    }
    // fill Xs
    for (int i = tid; i < 64 * 32; i += 256) {
        int c = i >> 5, p4 = (i & 31) << 2;
        *(float4*)&Xs[c * 128 + p4] = *(const float4*)(xb + (size_t)c * HW + p4);
    }
    __syncthreads();

    const int pt = tid & 15;   // pixel group: pixels pt*8 + [0..8)
    const int ot = tid >> 4;   // out group:   o = ot*8 + [0..8)
    u64 acc[8][4];             // [oi][pixel-pair pj]
    #pragma unroll
    for (int i = 0; i < 8; i++)
        #pragma unroll
        for (int j = 0; j < 4; j++) acc[i][j] = 0ULL;

    #pragma unroll 8
    for (int c = 0; c < 64; c++) {
        ulonglong2 xa = *(ulonglong2*)&Xs[c * 128 + pt * 8];
        ulonglong2 xb2 = *(ulonglong2*)&Xs[c * 128 + pt * 8 + 4];
        u64 xp[4] = {xa.x, xa.y, xb2.x, xb2.y};
        const u64* wp = Wd + c * 128 + ot * 8;
        ulonglong2 w01 = *(ulonglong2*)(wp);
        ulonglong2 w23 = *(ulonglong2*)(wp + 2);
        ulonglong2 w45 = *(ulonglong2*)(wp + 4);
        ulonglong2 w67 = *(ulonglong2*)(wp + 6);
        u64 wv[8] = {w01.x, w01.y, w23.x, w23.y, w45.x, w45.y, w67.x, w67.y};
        #pragma unroll
        for (int oi = 0; oi < 8; oi++)
            #pragma unroll
            for (int pj = 0; pj < 4; pj++)
                ffma2(acc[oi][pj], xp[pj], wv[oi]);
    }
    __syncthreads();

    // stage [pix][o ^ swizzle] (scalar stores; pairs are pixel-adjacent)
    #pragma unroll
    for (int oi = 0; oi < 8; oi++) {
        int o = ot * 8 + oi;
        #pragma unroll
        for (int pj = 0; pj < 4; pj++) {
            float lo, hi; unpack2(lo, hi, acc[oi][pj]);
            int pix0 = pt * 8 + 2 * pj;
            int z0 = ((pix0 >> 3) & 7) << 3;
            sm[pix0 * 128 + (o ^ z0)] = lo;
            int pix1 = pix0 + 1;
            int z1 = ((pix1 >> 3) & 7) << 3;
            sm[pix1 * 128 + (o ^ z1)] = hi;
        }
    }
    __syncthreads();

    for (int i2 = tid; i2 < 128 * 64; i2 += 256) {
        int pix = i2 >> 6;
        int o = (i2 & 63) * 2;
        int z = ((pix >> 3) & 7) << 3;
        float2 v = *(float2*)&sm[pix * 128 + (o ^ z)];
        *(float2*)&g_hidden[((size_t)b * HW + (size_t)pb * 128 + pix) * CH + ob * 128 + o] = v;
    }
}

// ---------------------------------------------------------------------------
// K2: per-patch dwconv + 8x8 circular conv + LN + gate + 1x1 conv out.
//   grid (32, 32, 4), block 128 (thread = channel). 34304 B dynamic smem.
// ---------------------------------------------------------------------------
__device__ __forceinline__ void loadrow10(float* r, const float* hid, int y, int x0, int c) {
    if ((unsigned)y < 256u) {
        #pragma unroll
        for (int j = 0; j < 10; j++) {
            int xx = x0 - 1 + j;
            r[j] = ((unsigned)xx < 256u) ? hid[((size_t)y * IMGW + xx) * CH + c] : 0.f;
        }
    } else {
        #pragma unroll
        for (int j = 0; j < 10; j++) r[j] = 0.f;
    }
}

// depthwise conv of channel c over an 8x8 patch -> smem (stride 128)
__device__ __forceinline__ void dwconv_smem(const float* hid, int c, int y0, int x0,
                                            float* sdst) {
    float w9[9];
    #pragma unroll
    for (int k = 0; k < 9; k++) w9[k] = g_wdw_t[k * 384 + c];
    float r0[10], r1[10], r2[10];
    loadrow10(r0, hid, y0 - 1, x0, c);
    loadrow10(r1, hid, y0,     x0, c);
    #pragma unroll
    for (int oy = 0; oy < 8; oy++) {
        loadrow10(r2, hid, y0 + oy + 1, x0, c);
        #pragma unroll
        for (int ox = 0; ox < 8; ox++) {
            float s = r0[ox] * w9[0] + r0[ox + 1] * w9[1] + r0[ox + 2] * w9[2]
                    + r1[ox] * w9[3] + r1[ox + 1] * w9[4] + r1[ox + 2] * w9[5]
                    + r2[ox] * w9[6] + r2[ox + 1] * w9[7] + r2[ox + 2] * w9[8];
            sdst[(oy * 8 + ox) * 128] = s;
        }
        #pragma unroll
        for (int j = 0; j < 10; j++) { r0[j] = r1[j]; r1[j] = r2[j]; }
    }
}

__global__ __launch_bounds__(128, 3) void k2_patch(const float* __restrict__ nw_g,
                                                   const float* __restrict__ nb_g,
                                                   float* __restrict__ out) {
    extern __shared__ float sm2[];
    float* sk  = sm2;                 // 64*128 (k; then pre-LN out; then gated; then staging)
    float* sA  = sm2 + 8192;          // 128 partial sums
    float* sB  = sm2 + 8320;          // 128 partial sq-sums
    float* smu = sm2 + 8448;          // 64
    float* srs = sm2 + 8512;          // 64

    const int b = blockIdx.z, py = blockIdx.y, px = blockIdx.x;
    const int t = threadIdx.x;
    const float* hid = g_hidden + (size_t)b * HW * CH;
    const int y0 = py * 8, x0 = px * 8;

    // ---- phase 1: k (ch 128+t) dwconv into own smem column (no sync needed) ----
    dwconv_smem(hid, 128 + t, y0, x0, sk + t);

    // ---- phase 2: q (ch t) dwconv streamed into scalar 8x8 circular conv ----
    float acc[64];
    #pragma unroll
    for (int i = 0; i < 64; i++) acc[i] = 0.f;
    {
        float w9[9];
        #pragma unroll
        for (int k = 0; k < 9; k++) w9[k] = g_wdw_t[k * 384 + t];
        const float* skt = sk + t;
        float r0[10], r1[10], r2[10];
        loadrow10(r0, hid, y0 - 1, x0, t);
        loadrow10(r1, hid, y0,     x0, t);
        #pragma unroll
        for (int oy = 0; oy < 8; oy++) {
            loadrow10(r2, hid, y0 + oy + 1, x0, t);
            float qr[8];
            #pragma unroll
            for (int ox = 0; ox < 8; ox++) {
                qr[ox] = r0[ox] * w9[0] + r0[ox + 1] * w9[1] + r0[ox + 2] * w9[2]
                       + r1[ox] * w9[3] + r1[ox + 1] * w9[4] + r1[ox + 2] * w9[5]
                       + r2[ox] * w9[6] + r2[ox + 1] * w9[7] + r2[ox + 2] * w9[8];
            }
            #pragma unroll
            for (int j = 0; j < 10; j++) { r0[j] = r1[j]; r1[j] = r2[j]; }

            #pragma unroll
            for (int u = 0; u < 8; u++) {
                float kr[8];
                #pragma unroll
                for (int v = 0; v < 8; v++) kr[v] = skt[(u * 8 + v) * 128];
                const int r = (u + oy) & 7;
                #pragma unroll
                for (int bb = 0; bb < 8; bb++)
                    #pragma unroll
                    for (int v = 0; v < 8; v++)
                        acc[(r << 3) + ((v + bb) & 7)] += qr[bb] * kr[v];
            }
        }
    }

    // ---- phase 3: acc -> sk (overwrite k; own column, conflict-free) ----
    #pragma unroll
    for (int p = 0; p < 64; p++) sk[p * 128 + t] = acc[p];
    __syncthreads();

    // ---- phase 4: LN stats per pixel, two-stage over thread halves ----
    {
        const int p = t & 63, h = t >> 6;
        float s = 0.f, s2 = 0.f;
        #pragma unroll 8
        for (int i = 0; i < 64; i++) {
            int c = h * 64 + i;
            float v = sk[p * 128 + ((c + p) & 127)];
            s += v; s2 += v * v;
        }
        sA[t] = s; sB[t] = s2;
    }
    __syncthreads();
    if (t < 64) {
        float s  = sA[t] + sA[t + 64];
        float s2 = sB[t] + sB[t + 64];
        float mu = s * (1.f / 128.f);
        float var = s2 * (1.f / 128.f) - mu * mu;
        smu[t] = mu;
        srs[t] = rsqrtf(var + 1e-5f);
    }
    __syncthreads();

    // ---- phase 5: v (ch 256+t) dwconv into regs, gate in place in sk ----
    {
        float w9[9];
        #pragma unroll
        for (int k = 0; k < 9; k++) w9[k] = g_wdw_t[k * 384 + 256 + t];
        float r0[10], r1[10], r2[10], vreg[64];
        loadrow10(r0, hid, y0 - 1, x0, 256 + t);
        loadrow10(r1, hid, y0,     x0, 256 + t);
        #pragma unroll
        for (int oy = 0; oy < 8; oy++) {
            loadrow10(r2, hid, y0 + oy + 1, x0, 256 + t);
            #pragma unroll
            for (int ox = 0; ox < 8; ox++) {
                vreg[oy * 8 + ox] =
                      r0[ox] * w9[0] + r0[ox + 1] * w9[1] + r0[ox + 2] * w9[2]
                    + r1[ox] * w9[3] + r1[ox + 1] * w9[4] + r1[ox + 2] * w9[5]
                    + r2[ox] * w9[6] + r2[ox + 1] * w9[7] + r2[ox + 2] * w9[8];
            }
            #pragma unroll
            for (int j = 0; j < 10; j++) { r0[j] = r1[j]; r1[j] = r2[j]; }
        }
        float nw = nw_g[t], nb = nb_g[t];
        #pragma unroll
        for (int p = 0; p < 64; p++) {
            float nrm = (sk[p * 128 + t] - smu[p]) * srs[p] * nw + nb;
            sk[p * 128 + t] = vreg[p] * nrm;    // gated (own column, in place)
        }
    }
    __syncthreads();

    // ---- phase 6: final 1x1 conv 128->64, f32x2 over channel pairs,
    //      gated read as broadcast LDS.128 (4 channels at once) ----
    {
        const int o = t & 63, ph = t >> 6, p0 = ph << 5;
        u64 pa[32];
        #pragma unroll
        for (int p = 0; p < 32; p++) pa[p] = 0ULL;
        #pragma unroll 2
        for (int c4 = 0; c4 < 32; c4++) {
            float2 w01 = __ldg(&g_wout_p[(2 * c4) * 64 + o]);
            float2 w23 = __ldg(&g_wout_p[(2 * c4 + 1) * 64 + o]);
            u64 wq01 = pack2(w01.x, w01.y);
            u64 wq23 = pack2(w23.x, w23.y);
            const float* gk = sk + 4 * c4;
            #pragma unroll
            for (int p = 0; p < 32; p++) {
                ulonglong2 g = *(const ulonglong2*)(gk + (p0 + p) * 128);
                ffma2(pa[p], g.x, wq01);
                ffma2(pa[p], g.y, wq23);
            }
        }
        __syncthreads();   // all reads of gated done before staging overwrites sk
        #pragma unroll
        for (int p = 0; p < 32; p++) {
            float lo, hi; unpack2(lo, hi, pa[p]);
            sk[o * 66 + p0 + p] = lo + hi;
        }
    }
    __syncthreads();

    // ---- phase 7: coalesced write-out ----
    for (int i = t; i < 4096; i += 128) {
        int oo = i >> 6, p = i & 63;
        int y = y0 + (p >> 3), x = x0 + (p & 7);
        out[(((size_t)b * 64 + oo) * IMGW + y) * IMGW + x] = sk[oo * 66 + p];
    }
}

// ---------------------------------------------------------------------------
extern "C" void kernel_launch(void* const* d_in, const int* in_sizes, int n_in,
                              void* d_out, int out_size) {
    const float* x    = (const float*)d_in[0];
    const float* wh   = (const float*)d_in[1];
    const float* wdw  = (const float*)d_in[2];
    const float* nw   = (const float*)d_in[3];
    const float* nb   = (const float*)d_in[4];
    const float* wout = (const float*)d_in[5];
    float* out = (float*)d_out;

    cudaFuncSetAttribute(k1_conv1x1, cudaFuncAttributeMaxDynamicSharedMemorySize, 98304);
    cudaFuncSetAttribute(k2_patch,   cudaFuncAttributeMaxDynamicSharedMemorySize, 34304);

    k1_conv1x1<<<dim3(512, 3, 4), 256, 98304>>>(x, wh, wdw, wout);
    k2_patch<<<dim3(32, 32, 4), 128, 34304>>>(nw, nb, out);
}

// round 12
// speedup vs baseline: 1.4448x; 1.4448x over previous
#include <cuda_runtime.h>
#include <cstdint>

#define HW 65536
#define IMGW 256
#define CH 384

// hidden activations, channel-last: [b][pix][384]  (402.7 MB)
__device__ float g_hidden[(size_t)4 * HW * CH];
__device__ float g_wdw_t[9 * 384];       // [tap][channel]
__device__ float2 g_wout_p[64 * 64];     // [c2][o] = (wout[o][2c2], wout[o][2c2+1])

typedef unsigned long long u64;

__device__ __forceinline__ u64 pack2(float lo, float hi) {
    u64 r; asm("mov.b64 %0, {%1, %2};" : "=l"(r) : "f"(lo), "f"(hi)); return r;
}
__device__ __forceinline__ void ffma2(u64 &d, u64 a, u64 b) {
    asm("fma.rn.f32x2 %0, %1, %2, %0;" : "+l"(d) : "l"(a), "l"(b));
}
__device__ __forceinline__ void unpack2(float &lo, float &hi, u64 v) {
    asm("mov.b64 {%0, %1}, %2;" : "=f"(lo), "=f"(hi) : "l"(v));
}

// ---------------------------------------------------------------------------
// K1: 1x1 conv 64->384 as SGEMM (f32x2 FMAs) — exact R6 form (measured 388us).
//   grid (512, 3, 4), block 256, 64KB dynamic smem, 3 CTAs/SM (24 warps).
//   Block (0,0,0) additionally preps g_wdw_t / g_wout_p for K2.
// ---------------------------------------------------------------------------
__global__ __launch_bounds__(256) void k1_conv1x1(const float* __restrict__ x,
                                                  const float* __restrict__ wh,
                                                  const float* __restrict__ wdw,
                                                  const float* __restrict__ wout) {
    extern __shared__ float sm[];
    float* Ws = sm;              // [64 c][128 o]
    float* Xs = sm + 64 * 128;   // [64 c][128 pix]
    const int b  = blockIdx.z;
    const int ob = blockIdx.y;
    const int pb = blockIdx.x;
    const int tid = threadIdx.x;

    if (pb == 0 && ob == 0 && b == 0) {
        for (int i = tid; i < 9 * 384; i += 256) {
            int o = i / 9, k = i % 9;
            g_wdw_t[k * 384 + o] = wdw[i];
        }
        for (int i = tid; i < 64 * 64; i += 256) {
            int c2 = i >> 6, o = i & 63;
            g_wout_p[c2 * 64 + o] = make_float2(wout[o * 128 + 2 * c2],
                                                wout[o * 128 + 2 * c2 + 1]);
        }
    }

    const float* xb = x + (size_t)b * 64 * HW + (size_t)pb * 128;

    for (int i = tid; i < 128 * 16; i += 256) {
        int o = i >> 4, c4 = (i & 15) << 2;
        float4 v = *(const float4*)(wh + (size_t)(ob * 128 + o) * 64 + c4);
        Ws[(c4 + 0) * 128 + o] = v.x; Ws[(c4 + 1) * 128 + o] = v.y;
        Ws[(c4 + 2) * 128 + o] = v.z; Ws[(c4 + 3) * 128 + o] = v.w;
    }
    for (int i = tid; i < 64 * 32; i += 256) {
        int c = i >> 5, p4 = (i & 31) << 2;
        *(float4*)&Xs[c * 128 + p4] = *(const float4*)(xb + (size_t)c * HW + p4);
    }
    __syncthreads();

    const int pt = tid & 15;   // pixel group: pix = pt*8 + i
    const int ot = tid >> 4;   // out group:   o   = ot*8 + 2j
    u64 acc[8][4];
    #pragma unroll
    for (int i = 0; i < 8; i++)
        #pragma unroll
        for (int j = 0; j < 4; j++) acc[i][j] = 0ULL;

    #pragma unroll 8
    for (int c = 0; c < 64; c++) {
        float4 a0 = *(float4*)&Xs[c * 128 + pt * 8];
        float4 a1 = *(float4*)&Xs[c * 128 + pt * 8 + 4];
        u64 bq[4];
        #pragma unroll
        for (int j = 0; j < 4; j++) bq[j] = *(u64*)&Ws[c * 128 + ot * 8 + 2 * j];
        float av[8] = {a0.x, a0.y, a0.z, a0.w, a1.x, a1.y, a1.z, a1.w};
        #pragma unroll
        for (int i = 0; i < 8; i++) {
            u64 ad = pack2(av[i], av[i]);
            #pragma unroll
            for (int j = 0; j < 4; j++) ffma2(acc[i][j], ad, bq[j]);
        }
    }
    __syncthreads();

    // stage [pix][o ^ swizzle] for conflict-free + coalesced write-out
    #pragma unroll
    for (int i = 0; i < 8; i++) {
        int pix = pt * 8 + i;
        int z = ((pix >> 3) & 7) << 3;
        #pragma unroll
        for (int j = 0; j < 4; j++) {
            int o = ot * 8 + 2 * j;
            *(u64*)&sm[pix * 128 + (o ^ z)] = acc[i][j];
        }
    }
    __syncthreads();

    for (int i2 = tid; i2 < 128 * 64; i2 += 256) {
        int pix = i2 >> 6;
        int o = (i2 & 63) * 2;
        int z = ((pix >> 3) & 7) << 3;
        float2 v = *(float2*)&sm[pix * 128 + (o ^ z)];
        *(float2*)&g_hidden[((size_t)b * HW + (size_t)pb * 128 + pix) * CH + ob * 128 + o] = v;
    }
}

// ---------------------------------------------------------------------------
// K2: per-patch dwconv + 8x8 circular conv + LN + gate + 1x1 conv out.
//   grid (32, 32, 4), block 256 = (channel 0..127) x (row-half 0..1).
//   Each thread handles 4 of 8 patch rows of one channel -> half the work and
//   half the registers of the 128-thread version; 2 CTAs/SM = 16 warps.
//   smem (floats): sq[8192] | sk[8192] | sA[256] | sB[256] | smu[64] | srs[64]
// ---------------------------------------------------------------------------
__device__ __forceinline__ void loadrow10(float* r, const float* hid, int y, int x0, int c) {
    if ((unsigned)y < 256u) {
        #pragma unroll
        for (int j = 0; j < 10; j++) {
            int xx = x0 - 1 + j;
            r[j] = ((unsigned)xx < 256u) ? hid[((size_t)y * IMGW + xx) * CH + c] : 0.f;
        }
    } else {
        #pragma unroll
        for (int j = 0; j < 10; j++) r[j] = 0.f;
    }
}

// depthwise conv of channel c, output rows oy0..oy0+3 -> smem column (stride 128)
__device__ __forceinline__ void dwconv_half(const float* hid, int c, int y0, int x0,
                                            int oy0, float* sdst) {
    float w9[9];
    #pragma unroll
    for (int k = 0; k < 9; k++) w9[k] = g_wdw_t[k * 384 + c];
    float r0[10], r1[10], r2[10];
    loadrow10(r0, hid, y0 + oy0 - 1, x0, c);
    loadrow10(r1, hid, y0 + oy0,     x0, c);
    #pragma unroll
    for (int oy = 0; oy < 4; oy++) {
        loadrow10(r2, hid, y0 + oy0 + oy + 1, x0, c);
        #pragma unroll
        for (int ox = 0; ox < 8; ox++) {
            float s = r0[ox] * w9[0] + r0[ox + 1] * w9[1] + r0[ox + 2] * w9[2]
                    + r1[ox] * w9[3] + r1[ox + 1] * w9[4] + r1[ox + 2] * w9[5]
                    + r2[ox] * w9[6] + r2[ox + 1] * w9[7] + r2[ox + 2] * w9[8];
            sdst[((oy0 + oy) * 8 + ox) * 128] = s;
        }
        #pragma unroll
        for (int j = 0; j < 10; j++) { r0[j] = r1[j]; r1[j] = r2[j]; }
    }
}

__global__ __launch_bounds__(256, 2) void k2_patch(const float* __restrict__ nw_g,
                                                   const float* __restrict__ nb_g,
                                                   float* __restrict__ out) {
    extern __shared__ float sm2[];
    float* sq  = sm2;                 // q; then pre-LN out; then out staging
    float* sk  = sm2 + 8192;          // k; then gated
    float* sA  = sm2 + 16384;         // 256 partial sums
    float* sB  = sm2 + 16640;         // 256 partial sq-sums
    float* smu = sm2 + 16896;         // 64
    float* srs = sm2 + 16960;         // 64

    const int b = blockIdx.z, py = blockIdx.y, px = blockIdx.x;
    const int t = threadIdx.x;
    const int ch = t & 127, h = t >> 7;
    const int oy0 = 4 * h;
    const float* hid = g_hidden + (size_t)b * HW * CH;
    const int y0 = py * 8, x0 = px * 8;

    // ---- phase 1: q (ch) and k (128+ch) dwconv halves into smem ----
    dwconv_half(hid, ch,       y0, x0, oy0, sq + ch);
    dwconv_half(hid, 128 + ch, y0, x0, oy0, sk + ch);
    __syncthreads();

    // ---- phase 2: circular conv, this thread computes out rows oy0..oy0+3 ----
    float acc[32];
    #pragma unroll
    for (int i = 0; i < 32; i++) acc[i] = 0.f;
    {
        const float* sqc = sq + ch;
        const float* skc = sk + ch;
        #pragma unroll
        for (int a = 0; a < 8; a++) {
            float qr[8];
            #pragma unroll
            for (int bb = 0; bb < 8; bb++) qr[bb] = sqc[(a * 8 + bb) * 128];
            #pragma unroll
            for (int i = 0; i < 4; i++) {
                const int u = (oy0 + i - a) & 7;
                float kr[8];
                #pragma unroll
                for (int v = 0; v < 8; v++) kr[v] = skc[(u * 8 + v) * 128];
                #pragma unroll
                for (int bb = 0; bb < 8; bb++)
                    #pragma unroll
                    for (int v = 0; v < 8; v++)
                        acc[(i << 3) + ((bb + v) & 7)] += qr[bb] * kr[v];
            }
        }
    }
    __syncthreads();   // all circconv reads of sq/sk complete

    // ---- phase 3: acc -> sq (pre-LN out) ----
    #pragma unroll
    for (int i = 0; i < 32; i++) sq[(oy0 * 8 + i) * 128 + ch] = acc[i];
    __syncthreads();

    // ---- phase 4: LN stats per pixel, 4-way channel partials ----
    {
        const int p = t & 63, g4 = t >> 6;
        float s = 0.f, s2 = 0.f;
        #pragma unroll 8
        for (int i = 0; i < 32; i++) {
            int c = g4 * 32 + i;
            float v = sq[p * 128 + ((c + p) & 127)];
            s += v; s2 += v * v;
        }
        sA[g4 * 64 + p] = s; sB[g4 * 64 + p] = s2;
    }
    __syncthreads();
    if (t < 64) {
        float s  = sA[t] + sA[t + 64] + sA[t + 128] + sA[t + 192];
        float s2 = sB[t] + sB[t + 64] + sB[t + 128] + sB[t + 192];
        float mu = s * (1.f / 128.f);
        float var = s2 * (1.f / 128.f) - mu * mu;
        smu[t] = mu;
        srs[t] = rsqrtf(var + 1e-5f);
    }
    __syncthreads();

    // ---- phase 5: v (256+ch) dwconv half, gate -> sk ----
    {
        float w9[9];
        #pragma unroll
        for (int k = 0; k < 9; k++) w9[k] = g_wdw_t[k * 384 + 256 + ch];
        float r0[10], r1[10], r2[10], vreg[32];
        loadrow10(r0, hid, y0 + oy0 - 1, x0, 256 + ch);
        loadrow10(r1, hid, y0 + oy0,     x0, 256 + ch);
        #pragma unroll
        for (int oy = 0; oy < 4; oy++) {
            loadrow10(r2, hid, y0 + oy0 + oy + 1, x0, 256 + ch);
            #pragma unroll
            for (int ox = 0; ox < 8; ox++) {
                vreg[oy * 8 + ox] =
                      r0[ox] * w9[0] + r0[ox + 1] * w9[1] + r0[ox + 2] * w9[2]
                    + r1[ox] * w9[3] + r1[ox + 1] * w9[4] + r1[ox + 2] * w9[5]
                    + r2[ox] * w9[6] + r2[ox + 1] * w9[7] + r2[ox + 2] * w9[8];
            }
            #pragma unroll
            for (int j = 0; j < 10; j++) { r0[j] = r1[j]; r1[j] = r2[j]; }
        }
        float nw = nw_g[ch], nb = nb_g[ch];
        #pragma unroll
        for (int i = 0; i < 32; i++) {
            int p = oy0 * 8 + i;
            float nrm = (sq[p * 128 + ch] - smu[p]) * srs[p] * nw + nb;
            sk[p * 128 + ch] = vreg[i] * nrm;
        }
    }
    __syncthreads();

    // ---- phase 6: final 1x1 conv 128->64, f32x2, broadcast LDS.128 reads;
    //      16 pixels per thread; stage into sq (dead) ----
    {
        const int o = t & 63, ph = t >> 6, p0 = ph << 4;
        u64 pa[16];
        #pragma unroll
        for (int p = 0; p < 16; p++) pa[p] = 0ULL;
        #pragma unroll 2
        for (int c4 = 0; c4 < 32; c4++) {
            float2 w01 = __ldg(&g_wout_p[(2 * c4) * 64 + o]);
            float2 w23 = __ldg(&g_wout_p[(2 * c4 + 1) * 64 + o]);
            u64 wq01 = pack2(w01.x, w01.y);
            u64 wq23 = pack2(w23.x, w23.y);
            const float* gk = sk + 4 * c4;
            #pragma unroll
            for (int p = 0; p < 16; p++) {
                ulonglong2 g = *(const ulonglong2*)(gk + (p0 + p) * 128);
                ffma2(pa[p], g.x, wq01);
                ffma2(pa[p], g.y, wq23);
            }
        }
        // staging writes sq; phase 6 reads only sk -> no barrier needed
        #pragma unroll
        for (int p = 0; p < 16; p++) {
            float lo, hi; unpack2(lo, hi, pa[p]);
            sq[o * 66 + p0 + p] = lo + hi;
        }
    }
    __syncthreads();

    // ---- phase 7: coalesced write-out ----
    for (int i = t; i < 4096; i += 256) {
        int oo = i >> 6, p = i & 63;
        int y = y0 + (p >> 3), x = x0 + (p & 7);
        out[(((size_t)b * 64 + oo) * IMGW + y) * IMGW + x] = sq[oo * 66 + p];
    }
}

// ---------------------------------------------------------------------------
extern "C" void kernel_launch(void* const* d_in, const int* in_sizes, int n_in,
                              void* d_out, int out_size) {
    const float* x    = (const float*)d_in[0];
    const float* wh   = (const float*)d_in[1];
    const float* wdw  = (const float*)d_in[2];
    const float* nw   = (const float*)d_in[3];
    const float* nb   = (const float*)d_in[4];
    const float* wout = (const float*)d_in[5];
    float* out = (float*)d_out;

    cudaFuncSetAttribute(k1_conv1x1, cudaFuncAttributeMaxDynamicSharedMemorySize, 65536);
    cudaFuncSetAttribute(k2_patch,   cudaFuncAttributeMaxDynamicSharedMemorySize, 68096);

    k1_conv1x1<<<dim3(512, 3, 4), 256, 65536>>>(x, wh, wdw, wout);
    k2_patch<<<dim3(32, 32, 4), 256, 68096>>>(nw, nb, out);
}